// round 12
// baseline (speedup 1.0000x reference)
#include <cuda_runtime.h>
#include <cuda_bf16.h>
#include <cuda_fp16.h>

#define MAXN 100000
#define MAXE 1600000
#define FIN 128
#define HH 64
#define NB_MAX 512

// GEMM smem layout (bytes, per stage): A fp32 128x40, B hi/lo bf16 128x40 each
#define AF_BYTES 20480
#define BH_BYTES 10240
#define STAGE_BYTES (AF_BYTES + 2 * BH_BYTES)   // 40960
#define DSMEM_BYTES (2 * STAGE_BYTES)           // 81920

// ---------------- device scratch ----------------
__device__ int    g_is64;
__device__ int    g_deg[MAXN];
__device__ int    g_rowstart[MAXN];
__device__ int    g_cursor[MAXN];
__device__ int    g_src[MAXE];
__device__ int    g_part[NB_MAX];
__device__ float  g_dinv[MAXN];
__device__ __half g_xsh[MAXN * 64];            // fp16 RAW (x@W1), 128B/row
__device__ float4 g_xf[MAXN * 16];             // (x@Wf1)[n] + bf1
__device__ float  g_u [MAXN];
__device__ __nv_bfloat16 g_Wthi[128 * 128];
__device__ __nv_bfloat16 g_Wtlo[128 * 128];

// ---------------- prepA: detect + part init + zero_deg ----------------
__global__ void prepA_kernel(const unsigned long long* __restrict__ p, int nwords, int N) {
    int b = blockIdx.x, t = threadIdx.x;
    if (b == 0) {
        int bad = 0;
        for (int i = t; i < nwords; i += 256)
            if (p[i] >= (1ULL << 32)) bad = 1;
        bad = __syncthreads_or(bad);
        if (t == 0) g_is64 = bad ? 0 : 1;
        g_part[t] = -1;
        g_part[256 + t] = -1;
    } else {
        int n = (b - 1) * 256 + t;
        if (n < N) g_deg[n] = 0;
    }
}

// ---------------- wprep: weight split+transpose ----------------
__global__ void wprep_kernel(const float* __restrict__ W1, const float* __restrict__ Wf1) {
    int idx = blockIdx.x * 256 + threadIdx.x;
    if (idx >= 128 * 128) return;
    int k = idx >> 7;
    int n = idx & 127;
    float v = (n < HH) ? W1[k * HH + n] : Wf1[k * HH + (n - HH)];
    __nv_bfloat16 hi = __float2bfloat16(v);
    float lo = v - __bfloat162float(hi);
    g_Wthi[n * 128 + k] = hi;
    g_Wtlo[n * 128 + k] = __float2bfloat16(lo);
}

// ---------------- count (8 edges/thread) ----------------
__global__ void count_kernel(const void* __restrict__ ei, long long E) {
    long long base = (blockIdx.x * 256LL + threadIdx.x) * 8;
    if (base >= E) return;
    if (g_is64) {
        const long long* p = (const long long*)ei + E;
        if (base + 8 <= E) {
            #pragma unroll
            for (int j = 0; j < 8; j += 2) {
                longlong2 a = *(const longlong2*)&p[base + j];
                atomicAdd(&g_deg[(int)a.x], 1);
                atomicAdd(&g_deg[(int)a.y], 1);
            }
        } else {
            for (long long e = base; e < E; e++) atomicAdd(&g_deg[(int)p[e]], 1);
        }
    } else {
        const int* p = (const int*)ei + E;
        if (base + 8 <= E) {
            int4 v0 = *(const int4*)&p[base];
            int4 v1 = *(const int4*)&p[base + 4];
            atomicAdd(&g_deg[v0.x], 1); atomicAdd(&g_deg[v0.y], 1);
            atomicAdd(&g_deg[v0.z], 1); atomicAdd(&g_deg[v0.w], 1);
            atomicAdd(&g_deg[v1.x], 1); atomicAdd(&g_deg[v1.y], 1);
            atomicAdd(&g_deg[v1.z], 1); atomicAdd(&g_deg[v1.w], 1);
        } else {
            for (long long e = base; e < E; e++) atomicAdd(&g_deg[p[e]], 1);
        }
    }
}

// ---------------- single-pass scan ----------------
__global__ __launch_bounds__(256) void scan_kernel(int N) {
    __shared__ int s[256];
    __shared__ int wsum[8];
    __shared__ int prefix;
    int b = blockIdx.x, t = threadIdx.x;
    int n = b * 256 + t;
    int v = (n < N) ? g_deg[n] : 0;

    int w = v;
    #pragma unroll
    for (int o = 16; o > 0; o >>= 1) w += __shfl_xor_sync(0xFFFFFFFFu, w, o);
    if ((t & 31) == 0) wsum[t >> 5] = w;
    __syncthreads();
    if (t == 0) {
        int tot = 0;
        #pragma unroll
        for (int i = 0; i < 8; i++) tot += wsum[i];
        atomicExch(&g_part[b], tot);
    }
    __syncthreads();

    s[t] = v;
    __syncthreads();
    for (int off = 1; off < 256; off <<= 1) {
        int x = (t >= off) ? s[t - off] : 0;
        __syncthreads();
        s[t] += x;
        __syncthreads();
    }

    int p = 0;
    for (int i = t; i < b; i += 256) {
        int a;
        do { a = atomicAdd(&g_part[i], 0); } while (a < 0);
        p += a;
    }
    #pragma unroll
    for (int o = 16; o > 0; o >>= 1) p += __shfl_xor_sync(0xFFFFFFFFu, p, o);
    if ((t & 31) == 0) wsum[t >> 5] = p;
    __syncthreads();
    if (t == 0) {
        int pr = 0;
        #pragma unroll
        for (int i = 0; i < 8; i++) pr += wsum[i];
        prefix = pr;
    }
    __syncthreads();

    if (n < N) {
        int rs = prefix + s[t] - v;
        g_rowstart[n] = rs;
        g_cursor[n]   = rs;
        g_dinv[n]     = rsqrtf((float)(v + 1));
    }
}

// ---------------- scatter (8 edges/thread) ----------------
__global__ void scatter_kernel(const void* __restrict__ ei, long long E) {
    long long base = (blockIdx.x * 256LL + threadIdx.x) * 8;
    if (base >= E) return;
    int r[8], c[8];
    int cnt;
    if (g_is64) {
        const long long* pr = (const long long*)ei;
        const long long* pc = pr + E;
        if (base + 8 <= E) {
            #pragma unroll
            for (int j = 0; j < 8; j += 2) {
                longlong2 rv = *(const longlong2*)&pr[base + j];
                longlong2 cv = *(const longlong2*)&pc[base + j];
                r[j] = (int)rv.x; r[j + 1] = (int)rv.y;
                c[j] = (int)cv.x; c[j + 1] = (int)cv.y;
            }
            cnt = 8;
        } else {
            cnt = (int)(E - base);
            for (int i = 0; i < cnt; i++) { r[i] = (int)pr[base + i]; c[i] = (int)pc[base + i]; }
        }
    } else {
        const int* pr = (const int*)ei;
        const int* pc = pr + E;
        if (base + 8 <= E) {
            int4 r0 = *(const int4*)&pr[base];
            int4 r1 = *(const int4*)&pr[base + 4];
            int4 c0 = *(const int4*)&pc[base];
            int4 c1 = *(const int4*)&pc[base + 4];
            r[0] = r0.x; r[1] = r0.y; r[2] = r0.z; r[3] = r0.w;
            r[4] = r1.x; r[5] = r1.y; r[6] = r1.z; r[7] = r1.w;
            c[0] = c0.x; c[1] = c0.y; c[2] = c0.z; c[3] = c0.w;
            c[4] = c1.x; c[5] = c1.y; c[6] = c1.z; c[7] = c1.w;
            cnt = 8;
        } else {
            cnt = (int)(E - base);
            for (int i = 0; i < cnt; i++) { r[i] = pr[base + i]; c[i] = pc[base + i]; }
        }
    }
    #pragma unroll
    for (int i = 0; i < 8; i++) {
        if (i < cnt) {
            int pos = atomicAdd(&g_cursor[c[i]], 1);
            g_src[pos] = r[i];
        }
    }
}

// ---------------- GEMM v4: cp.async fp32-A + convert-on-read ----------
__device__ __forceinline__ void mma16816(float* c, const unsigned* a, const unsigned* b) {
    asm volatile(
        "mma.sync.aligned.m16n8k16.row.col.f32.bf16.bf16.f32 "
        "{%0,%1,%2,%3}, {%4,%5,%6,%7}, {%8,%9}, {%0,%1,%2,%3};"
        : "+f"(c[0]), "+f"(c[1]), "+f"(c[2]), "+f"(c[3])
        : "r"(a[0]), "r"(a[1]), "r"(a[2]), "r"(a[3]), "r"(b[0]), "r"(b[1]));
}

__device__ __forceinline__ void cpa16(void* smem_dst, const void* gsrc) {
    unsigned d = (unsigned)__cvta_generic_to_shared(smem_dst);
    asm volatile("cp.async.cg.shared.global [%0], [%1], 16;" :: "r"(d), "l"(gsrc));
}
__device__ __forceinline__ void cpa16z(void* smem_dst, const void* gsrc, int sz) {
    unsigned d = (unsigned)__cvta_generic_to_shared(smem_dst);
    asm volatile("cp.async.cg.shared.global [%0], [%1], 16, %2;" :: "r"(d), "l"(gsrc), "r"(sz));
}

__device__ __forceinline__ void split2(float2 v, unsigned& h, unsigned& l) {
    __nv_bfloat162 hh = __floats2bfloat162_rn(v.x, v.y);
    float2 hf = __bfloat1622float2(hh);
    __nv_bfloat162 ll = __floats2bfloat162_rn(v.x - hf.x, v.y - hf.y);
    h = *(unsigned*)&hh;
    l = *(unsigned*)&ll;
}

__global__ __launch_bounds__(256, 2) void gemm_kernel(
    const float* __restrict__ x, const float* __restrict__ bf1, int N)
{
    extern __shared__ char dyn[];

    const int t    = threadIdx.x;
    const int lane = t & 31;
    const int wid  = t >> 5;
    const int g    = lane >> 2;
    const int tg   = lane & 3;
    const int warp_m = wid >> 2;
    const int warp_n = wid & 3;
    const int bm = blockIdx.x * 128;

    auto load_stage = [&](int kt, int s) {
        char* base = dyn + s * STAGE_BYTES;
        float* Af = (float*)base;
        __nv_bfloat16* Bh = (__nv_bfloat16*)(base + AF_BYTES);
        __nv_bfloat16* Bl = (__nv_bfloat16*)(base + AF_BYTES + BH_BYTES);
        int kc = kt * 32;
        #pragma unroll
        for (int i = 0; i < 4; i++) {
            int idx = i * 256 + t;
            int row = idx >> 3;
            int qf  = (idx & 7) * 4;
            int gm  = bm + row;
            const float* src = x + (long long)(gm < N ? gm : 0) * FIN + kc + qf;
            cpa16z(Af + row * 40 + qf, src, gm < N ? 16 : 0);
        }
        #pragma unroll
        for (int i = 0; i < 2; i++) {
            int idx = i * 256 + t;
            int n = idx >> 2;
            int q = (idx & 3) * 8;
            cpa16(Bh + n * 40 + q, g_Wthi + n * 128 + kc + q);
            cpa16(Bl + n * 40 + q, g_Wtlo + n * 128 + kc + q);
        }
    };

    float c[4][4][4];
    #pragma unroll
    for (int mi = 0; mi < 4; mi++)
        #pragma unroll
        for (int ni = 0; ni < 4; ni++)
            #pragma unroll
            for (int q = 0; q < 4; q++) c[mi][ni][q] = 0.f;

    load_stage(0, 0);
    asm volatile("cp.async.commit_group;" ::: "memory");
    load_stage(1, 1);
    asm volatile("cp.async.commit_group;" ::: "memory");
    asm volatile("cp.async.wait_group 1;" ::: "memory");
    __syncthreads();

    for (int kt = 0; kt < 4; kt++) {
        const int buf = kt & 1;
        const char* base = dyn + buf * STAGE_BYTES;
        const float* Af = (const float*)base;
        const __nv_bfloat16* Bh = (const __nv_bfloat16*)(base + AF_BYTES);
        const __nv_bfloat16* Bl = (const __nv_bfloat16*)(base + AF_BYTES + BH_BYTES);

        #pragma unroll
        for (int kh = 0; kh < 32; kh += 16) {
            unsigned bh[4][2], bl[4][2];
            #pragma unroll
            for (int ni = 0; ni < 4; ni++) {
                int bbase = (warp_n * 32 + ni * 8 + g) * 40 + kh + 2 * tg;
                bh[ni][0] = *(const unsigned*)&Bh[bbase];
                bh[ni][1] = *(const unsigned*)&Bh[bbase + 8];
                bl[ni][0] = *(const unsigned*)&Bl[bbase];
                bl[ni][1] = *(const unsigned*)&Bl[bbase + 8];
            }
            #pragma unroll
            for (int mi = 0; mi < 4; mi++) {
                int row0 = (warp_m * 64 + mi * 16 + g) * 40 + kh + 2 * tg;
                int row1 = row0 + 8 * 40;
                float2 v00 = *(const float2*)&Af[row0];
                float2 v10 = *(const float2*)&Af[row1];
                float2 v01 = *(const float2*)&Af[row0 + 8];
                float2 v11 = *(const float2*)&Af[row1 + 8];
                unsigned ah[4], al[4];
                split2(v00, ah[0], al[0]);
                split2(v10, ah[1], al[1]);
                split2(v01, ah[2], al[2]);
                split2(v11, ah[3], al[3]);
                #pragma unroll
                for (int ni = 0; ni < 4; ni++) {
                    mma16816(c[mi][ni], ah, bh[ni]);
                    mma16816(c[mi][ni], al, bh[ni]);
                    mma16816(c[mi][ni], ah, bl[ni]);
                }
            }
        }
        __syncthreads();
        if (kt < 2) {
            load_stage(kt + 2, buf);
            asm volatile("cp.async.commit_group;" ::: "memory");
            asm volatile("cp.async.wait_group 1;" ::: "memory");
            __syncthreads();
        } else if (kt == 2) {
            asm volatile("cp.async.wait_group 0;" ::: "memory");
            __syncthreads();
        }
    }

    float* xff = (float*)g_xf;
    #pragma unroll
    for (int mi = 0; mi < 4; mi++) {
        int rA = bm + warp_m * 64 + mi * 16 + g;
        int rB = rA + 8;
        #pragma unroll
        for (int ni = 0; ni < 4; ni++) {
            int col = warp_n * 32 + ni * 8 + 2 * tg;
            if (warp_n < 2) {
                if (rA < N)
                    *(__half2*)&g_xsh[(long long)rA * 64 + col] =
                        __floats2half2_rn(c[mi][ni][0], c[mi][ni][1]);
                if (rB < N)
                    *(__half2*)&g_xsh[(long long)rB * 64 + col] =
                        __floats2half2_rn(c[mi][ni][2], c[mi][ni][3]);
            } else {
                int cf = col - 64;
                float b0 = bf1[cf], b1v = bf1[cf + 1];
                if (rA < N)
                    *(float2*)&xff[(long long)rA * 64 + cf] =
                        make_float2(c[mi][ni][0] + b0, c[mi][ni][1] + b1v);
                if (rB < N)
                    *(float2*)&xff[(long long)rB * 64 + cf] =
                        make_float2(c[mi][ni][2] + b0, c[mi][ni][3] + b1v);
            }
        }
    }
}

// ---------------- aggfin v3: quarter-warp gather ----------------
// 4 edges in flight per warp (8-lane groups), each lane loads uint4 = 16B;
// 8 lanes x 16B = full 128B row per edge. Unrolled x2 -> 8 edges/iter.
__device__ __forceinline__ void acc8(float* a, uint4 u, float w) {
    float2 f0 = __half22float2(*(__half2*)&u.x);
    float2 f1 = __half22float2(*(__half2*)&u.y);
    float2 f2 = __half22float2(*(__half2*)&u.z);
    float2 f3 = __half22float2(*(__half2*)&u.w);
    a[0] = fmaf(w, f0.x, a[0]); a[1] = fmaf(w, f0.y, a[1]);
    a[2] = fmaf(w, f1.x, a[2]); a[3] = fmaf(w, f1.y, a[3]);
    a[4] = fmaf(w, f2.x, a[4]); a[5] = fmaf(w, f2.y, a[5]);
    a[6] = fmaf(w, f3.x, a[6]); a[7] = fmaf(w, f3.y, a[7]);
}

__global__ __launch_bounds__(256) void aggfin_kernel(
    const float* __restrict__ b1,
    const float* __restrict__ W2,  const float* __restrict__ b2,
    const float* __restrict__ Wf2, const float* __restrict__ bf2,
    float* __restrict__ out, int N)
{
    int gwarp = (blockIdx.x * 256 + threadIdx.x) >> 5;
    int lane  = threadIdx.x & 31;
    if (gwarp >= N) return;
    const int quarter = lane >> 3;
    const int q = lane & 7;

    const uint4* __restrict__ xsv = (const uint4*)g_xsh;   // 8 uint4 per row
    const float* __restrict__ dptr = g_dinv;
    const int*  __restrict__ srcp = g_src;

    float a0[8] = {0.f,0.f,0.f,0.f,0.f,0.f,0.f,0.f};
    float a1[8] = {0.f,0.f,0.f,0.f,0.f,0.f,0.f,0.f};

    const int rs   = g_rowstart[gwarp];
    const int rend = rs + g_deg[gwarp];

    int e = rs + quarter;
    for (; e + 4 < rend; e += 8) {
        int s0 = __ldg(srcp + e);
        int s1 = __ldg(srcp + e + 4);
        float w0 = __ldg(dptr + s0);
        float w1 = __ldg(dptr + s1);
        uint4 u0 = __ldg(xsv + s0 * 8 + q);
        uint4 u1 = __ldg(xsv + s1 * 8 + q);
        acc8(a0, u0, w0);
        acc8(a1, u1, w1);
    }
    for (; e < rend; e += 4) {
        int s0 = __ldg(srcp + e);
        float w0 = __ldg(dptr + s0);
        uint4 u0 = __ldg(xsv + s0 * 8 + q);
        acc8(a0, u0, w0);
    }

    #pragma unroll
    for (int i = 0; i < 8; i++) {
        a0[i] += a1[i];
        a0[i] += __shfl_xor_sync(0xFFFFFFFFu, a0[i], 8);
        a0[i] += __shfl_xor_sync(0xFFFFFFFFu, a0[i], 16);
    }

    float dv = dptr[gwarp];
    {   // self term (after combine: per-lane full sums, used per-lane only)
        uint4 u = __ldg(xsv + gwarp * 8 + q);
        acc8(a0, u, dv);
    }

    float s = 0.f, tt = 0.f;
    if (lane < 8) {
        int c0 = lane * 8;
        #pragma unroll
        for (int i = 0; i < 8; i++) {
            float a = fmaxf(fmaf(dv, a0[i], b1[c0 + i]), 0.f);
            s  = fmaf(a, W2[c0 + i], s);
            tt = fmaf(a, Wf2[c0 + i], tt);
        }
    } else if (lane < 16) {
        int q2 = lane - 8;
        float4 f0 = __ldg(&g_xf[(long long)gwarp * 16 + 2 * q2]);
        float4 f1 = __ldg(&g_xf[(long long)gwarp * 16 + 2 * q2 + 1]);
        float f[8] = {f0.x, f0.y, f0.z, f0.w, f1.x, f1.y, f1.z, f1.w};
        int c0 = 64 + q2 * 8;
        #pragma unroll
        for (int i = 0; i < 8; i++) {
            float a = fmaxf(f[i], 0.f);
            s  = fmaf(a, W2[c0 + i], s);
            tt = fmaf(a, Wf2[c0 + i], tt);
        }
    }
    #pragma unroll
    for (int o = 16; o > 0; o >>= 1) {
        s  += __shfl_xor_sync(0xFFFFFFFFu, s, o);
        tt += __shfl_xor_sync(0xFFFFFFFFu, tt, o);
    }
    if (lane == 0) {
        float u = dv * s;
        g_u[gwarp] = u;
        out[gwarp] = b2[0] + bf2[0] + tt + dv * u;
    }
}

// ---------------- layer-2 gather ----------------
__global__ __launch_bounds__(256) void fin2_kernel(float* __restrict__ out, int N) {
    int gwarp = (blockIdx.x * 256 + threadIdx.x) >> 5;
    int lane  = threadIdx.x & 31;
    if (gwarp >= N) return;
    int rs  = g_rowstart[gwarp];
    int deg = g_deg[gwarp];
    float acc = 0.f;
    for (int i = lane; i < deg; i += 32)
        acc += __ldg(&g_u[g_src[rs + i]]);
    #pragma unroll
    for (int o = 16; o > 0; o >>= 1)
        acc += __shfl_xor_sync(0xFFFFFFFFu, acc, o);
    if (lane == 0)
        out[gwarp] += g_dinv[gwarp] * acc;
}

// ---- launch: prepA[0] count[1] scan[2] scatter[3](profiled) wprep[4] gemm[5] ...
extern "C" void kernel_launch(void* const* d_in, const int* in_sizes, int n_in,
                              void* d_out, int out_size) {
    const float* x   = (const float*)d_in[0];
    const void*  ei  = d_in[1];
    const float* W1  = (const float*)d_in[2];
    const float* b1  = (const float*)d_in[3];
    const float* Wf1 = (const float*)d_in[4];
    const float* bf1 = (const float*)d_in[5];
    const float* W2  = (const float*)d_in[6];
    const float* b2  = (const float*)d_in[7];
    const float* Wf2 = (const float*)d_in[8];
    const float* bf2 = (const float*)d_in[9];
    float* out = (float*)d_out;

    int N = in_sizes[0] / FIN;
    long long E = (long long)in_sizes[1] / 2;
    int nb = (N + 255) / 256;
    int eb8 = (int)((E + 2047) / 2048);

    static cudaStream_t s1 = nullptr;
    static cudaEvent_t ev0 = nullptr, evB = nullptr;
    if (!s1) {
        cudaStreamCreateWithFlags(&s1, cudaStreamNonBlocking);
        cudaEventCreateWithFlags(&ev0, cudaEventDisableTiming);
        cudaEventCreateWithFlags(&evB, cudaEventDisableTiming);
        cudaFuncSetAttribute(gemm_kernel, cudaFuncAttributeMaxDynamicSharedMemorySize,
                             DSMEM_BYTES);
    }
    cudaStream_t s0 = 0;

    // fork s1 from capture origin via pure event (no kernel)
    cudaEventRecord(ev0, s0);
    cudaStreamWaitEvent(s1, ev0, 0);

    int nwords = (E < 2048) ? (int)E : 2048;
    // s1: full edge pipeline  [0..3]
    prepA_kernel<<<1 + nb, 256, 0, s1>>>((const unsigned long long*)ei, nwords, N);
    count_kernel<<<eb8, 256, 0, s1>>>(ei, E);
    scan_kernel<<<nb, 256, 0, s1>>>(N);
    scatter_kernel<<<eb8, 256, 0, s1>>>(ei, E);   // profiled slot (launch idx 3)
    cudaEventRecord(evB, s1);

    // s0: GEMM path  [4..5]
    wprep_kernel<<<64, 256, 0, s0>>>(W1, Wf1);
    gemm_kernel<<<(N + 127) / 128, 256, DSMEM_BYTES, s0>>>(x, bf1, N);

    // join  [6..7]
    cudaStreamWaitEvent(s0, evB, 0);
    int wb = (int)(((long long)N * 32 + 255) / 256);
    aggfin_kernel<<<wb, 256, 0, s0>>>(b1, W2, b2, Wf2, bf2, out, N);
    fin2_kernel<<<wb, 256, 0, s0>>>(out, N);
}

// round 14
// speedup vs baseline: 1.0355x; 1.0355x over previous
#include <cuda_runtime.h>
#include <cuda_bf16.h>
#include <cuda_fp16.h>

#define MAXN 100000
#define MAXE 1600000
#define FIN 128
#define HH 64
#define NB_MAX 512

// GEMM v5 smem layout:
//  Bh[128][136] Bl[128][136] bf16 (full K resident, 272B row stride, 8-half pad)
//  A stages: 2 x [64][36] fp32 (144B row stride)
#define BSTRIDE 136
#define ASTRIDE 36
#define BH_BYTES (128 * BSTRIDE * 2)          // 34816
#define AF_STAGE (64 * ASTRIDE * 4)           // 9216
#define SM_BH 0
#define SM_BL (SM_BH + BH_BYTES)              // 34816
#define SM_A0 (SM_BL + BH_BYTES)              // 69632
#define SM_A1 (SM_A0 + AF_STAGE)              // 78848
#define DSMEM_BYTES (SM_A1 + AF_STAGE)        // 88064 -> 2 CTAs/SM by smem

// ---------------- device scratch ----------------
__device__ int    g_is64;
__device__ int    g_deg[MAXN];
__device__ int    g_rowstart[MAXN];
__device__ int    g_cursor[MAXN];
__device__ int    g_src[MAXE];
__device__ int    g_part[NB_MAX];
__device__ float  g_dinv[MAXN];
__device__ __half g_xsh[MAXN * 64];            // fp16 RAW (x@W1), 128B/row
__device__ float4 g_xf[MAXN * 16];             // (x@Wf1)[n] + bf1
__device__ float  g_u [MAXN];
__device__ __nv_bfloat16 g_Wthi[128 * 128];
__device__ __nv_bfloat16 g_Wtlo[128 * 128];

// ---------------- prepA: detect + part init + zero_deg ----------------
__global__ void prepA_kernel(const unsigned long long* __restrict__ p, int nwords, int N) {
    int b = blockIdx.x, t = threadIdx.x;
    if (b == 0) {
        int bad = 0;
        for (int i = t; i < nwords; i += 256)
            if (p[i] >= (1ULL << 32)) bad = 1;
        bad = __syncthreads_or(bad);
        if (t == 0) g_is64 = bad ? 0 : 1;
        g_part[t] = -1;
        g_part[256 + t] = -1;
    } else {
        int n = (b - 1) * 256 + t;
        if (n < N) g_deg[n] = 0;
    }
}

// ---------------- wprep: weight split+transpose ----------------
__global__ void wprep_kernel(const float* __restrict__ W1, const float* __restrict__ Wf1) {
    int idx = blockIdx.x * 256 + threadIdx.x;
    if (idx >= 128 * 128) return;
    int k = idx >> 7;
    int n = idx & 127;
    float v = (n < HH) ? W1[k * HH + n] : Wf1[k * HH + (n - HH)];
    __nv_bfloat16 hi = __float2bfloat16(v);
    float lo = v - __bfloat162float(hi);
    g_Wthi[n * 128 + k] = hi;
    g_Wtlo[n * 128 + k] = __float2bfloat16(lo);
}

// ---------------- count (4 edges/thread) ----------------
__global__ void count_kernel(const void* __restrict__ ei, long long E) {
    long long base = (blockIdx.x * 256LL + threadIdx.x) * 4;
    if (base >= E) return;
    if (g_is64) {
        const long long* p = (const long long*)ei + E;
        if (base + 4 <= E) {
            longlong2 a = *(const longlong2*)&p[base];
            longlong2 b = *(const longlong2*)&p[base + 2];
            atomicAdd(&g_deg[(int)a.x], 1);
            atomicAdd(&g_deg[(int)a.y], 1);
            atomicAdd(&g_deg[(int)b.x], 1);
            atomicAdd(&g_deg[(int)b.y], 1);
        } else {
            for (long long e = base; e < E; e++) atomicAdd(&g_deg[(int)p[e]], 1);
        }
    } else {
        const int* p = (const int*)ei + E;
        if (base + 4 <= E) {
            int4 v = *(const int4*)&p[base];
            atomicAdd(&g_deg[v.x], 1);
            atomicAdd(&g_deg[v.y], 1);
            atomicAdd(&g_deg[v.z], 1);
            atomicAdd(&g_deg[v.w], 1);
        } else {
            for (long long e = base; e < E; e++) atomicAdd(&g_deg[p[e]], 1);
        }
    }
}

// ---------------- single-pass scan ----------------
__global__ __launch_bounds__(256) void scan_kernel(int N) {
    __shared__ int s[256];
    __shared__ int wsum[8];
    __shared__ int prefix;
    int b = blockIdx.x, t = threadIdx.x;
    int n = b * 256 + t;
    int v = (n < N) ? g_deg[n] : 0;

    int w = v;
    #pragma unroll
    for (int o = 16; o > 0; o >>= 1) w += __shfl_xor_sync(0xFFFFFFFFu, w, o);
    if ((t & 31) == 0) wsum[t >> 5] = w;
    __syncthreads();
    if (t == 0) {
        int tot = 0;
        #pragma unroll
        for (int i = 0; i < 8; i++) tot += wsum[i];
        atomicExch(&g_part[b], tot);
    }
    __syncthreads();

    s[t] = v;
    __syncthreads();
    for (int off = 1; off < 256; off <<= 1) {
        int x = (t >= off) ? s[t - off] : 0;
        __syncthreads();
        s[t] += x;
        __syncthreads();
    }

    int p = 0;
    for (int i = t; i < b; i += 256) {
        int a;
        do { a = atomicAdd(&g_part[i], 0); } while (a < 0);
        p += a;
    }
    #pragma unroll
    for (int o = 16; o > 0; o >>= 1) p += __shfl_xor_sync(0xFFFFFFFFu, p, o);
    if ((t & 31) == 0) wsum[t >> 5] = p;
    __syncthreads();
    if (t == 0) {
        int pr = 0;
        #pragma unroll
        for (int i = 0; i < 8; i++) pr += wsum[i];
        prefix = pr;
    }
    __syncthreads();

    if (n < N) {
        int rs = prefix + s[t] - v;
        g_rowstart[n] = rs;
        g_cursor[n]   = rs;
        g_dinv[n]     = rsqrtf((float)(v + 1));
    }
}

// ---------------- scatter (4 edges/thread) ----------------
__global__ void scatter_kernel(const void* __restrict__ ei, long long E) {
    long long base = (blockIdx.x * 256LL + threadIdx.x) * 4;
    if (base >= E) return;
    int r[4], c[4];
    int cnt;
    if (g_is64) {
        const long long* pr = (const long long*)ei;
        const long long* pc = pr + E;
        if (base + 4 <= E) {
            longlong2 r0 = *(const longlong2*)&pr[base];
            longlong2 r1 = *(const longlong2*)&pr[base + 2];
            longlong2 c0 = *(const longlong2*)&pc[base];
            longlong2 c1 = *(const longlong2*)&pc[base + 2];
            r[0] = (int)r0.x; r[1] = (int)r0.y; r[2] = (int)r1.x; r[3] = (int)r1.y;
            c[0] = (int)c0.x; c[1] = (int)c0.y; c[2] = (int)c1.x; c[3] = (int)c1.y;
            cnt = 4;
        } else {
            cnt = (int)(E - base);
            for (int i = 0; i < cnt; i++) { r[i] = (int)pr[base + i]; c[i] = (int)pc[base + i]; }
        }
    } else {
        const int* pr = (const int*)ei;
        const int* pc = pr + E;
        if (base + 4 <= E) {
            int4 rv = *(const int4*)&pr[base];
            int4 cv = *(const int4*)&pc[base];
            r[0] = rv.x; r[1] = rv.y; r[2] = rv.z; r[3] = rv.w;
            c[0] = cv.x; c[1] = cv.y; c[2] = cv.z; c[3] = cv.w;
            cnt = 4;
        } else {
            cnt = (int)(E - base);
            for (int i = 0; i < cnt; i++) { r[i] = pr[base + i]; c[i] = pc[base + i]; }
        }
    }
    #pragma unroll
    for (int i = 0; i < 4; i++) {
        if (i < cnt) {
            int pos = atomicAdd(&g_cursor[c[i]], 1);
            g_src[pos] = r[i];
        }
    }
}

// ---------------- GEMM v5b: 64x128 tile, B resident (fixed stride) ----------
__device__ __forceinline__ void mma16816(float* c, const unsigned* a, const unsigned* b) {
    asm volatile(
        "mma.sync.aligned.m16n8k16.row.col.f32.bf16.bf16.f32 "
        "{%0,%1,%2,%3}, {%4,%5,%6,%7}, {%8,%9}, {%0,%1,%2,%3};"
        : "+f"(c[0]), "+f"(c[1]), "+f"(c[2]), "+f"(c[3])
        : "r"(a[0]), "r"(a[1]), "r"(a[2]), "r"(a[3]), "r"(b[0]), "r"(b[1]));
}

__device__ __forceinline__ void cpa16(void* smem_dst, const void* gsrc) {
    unsigned d = (unsigned)__cvta_generic_to_shared(smem_dst);
    asm volatile("cp.async.cg.shared.global [%0], [%1], 16;" :: "r"(d), "l"(gsrc));
}
__device__ __forceinline__ void cpa16z(void* smem_dst, const void* gsrc, int sz) {
    unsigned d = (unsigned)__cvta_generic_to_shared(smem_dst);
    asm volatile("cp.async.cg.shared.global [%0], [%1], 16, %2;" :: "r"(d), "l"(gsrc), "r"(sz));
}

__device__ __forceinline__ void split2(float2 v, unsigned& h, unsigned& l) {
    __nv_bfloat162 hh = __floats2bfloat162_rn(v.x, v.y);
    float2 hf = __bfloat1622float2(hh);
    __nv_bfloat162 ll = __floats2bfloat162_rn(v.x - hf.x, v.y - hf.y);
    h = *(unsigned*)&hh;
    l = *(unsigned*)&ll;
}

__global__ __launch_bounds__(256, 3) void gemm_kernel(
    const float* __restrict__ x, const float* __restrict__ bf1, int N)
{
    extern __shared__ char dyn[];
    __nv_bfloat16* Bh = (__nv_bfloat16*)(dyn + SM_BH);
    __nv_bfloat16* Bl = (__nv_bfloat16*)(dyn + SM_BL);

    const int t    = threadIdx.x;
    const int lane = t & 31;
    const int wid  = t >> 5;
    const int g    = lane >> 2;
    const int tg   = lane & 3;
    const int warp_m = wid >> 2;       // 0..1 (32 rows each)
    const int warp_n = wid & 3;        // 0..3 (32 cols each)
    const int bm = blockIdx.x * 64;

    auto load_A = [&](int kt, int s) {
        float* Af = (float*)(dyn + (s ? SM_A1 : SM_A0));
        int kc = kt * 32;
        #pragma unroll
        for (int i = 0; i < 2; i++) {
            int idx = i * 256 + t;          // 0..511 chunks (64 rows x 8)
            int row = idx >> 3;
            int qf  = (idx & 7) * 4;
            int gm  = bm + row;
            const float* src = x + (long long)(gm < N ? gm : 0) * FIN + kc + qf;
            cpa16z(Af + row * ASTRIDE + qf, src, gm < N ? 16 : 0);
        }
    };

    // prologue: full B (hi+lo) + A stage 0 -> group0 ; A stage 1 -> group1
    #pragma unroll
    for (int i = 0; i < 8; i++) {
        int idx = i * 256 + t;              // 0..2047 chunks per array
        int n = idx >> 4;                   // row 0..127
        int j = (idx & 15) * 8;             // half offset 0..120
        cpa16(Bh + n * BSTRIDE + j, g_Wthi + n * 128 + j);
        cpa16(Bl + n * BSTRIDE + j, g_Wtlo + n * 128 + j);
    }
    load_A(0, 0);
    asm volatile("cp.async.commit_group;" ::: "memory");
    load_A(1, 1);
    asm volatile("cp.async.commit_group;" ::: "memory");
    asm volatile("cp.async.wait_group 1;" ::: "memory");
    __syncthreads();

    float c[2][4][4];
    #pragma unroll
    for (int mi = 0; mi < 2; mi++)
        #pragma unroll
        for (int ni = 0; ni < 4; ni++)
            #pragma unroll
            for (int q = 0; q < 4; q++) c[mi][ni][q] = 0.f;

    for (int kt = 0; kt < 4; kt++) {
        const float* Af = (const float*)(dyn + ((kt & 1) ? SM_A1 : SM_A0));
        #pragma unroll
        for (int kh = 0; kh < 32; kh += 16) {
            int kcol = kt * 32 + kh + 2 * tg;
            unsigned bh[4][2], bl[4][2];
            #pragma unroll
            for (int ni = 0; ni < 4; ni++) {
                int bbase = (warp_n * 32 + ni * 8 + g) * BSTRIDE + kcol;
                bh[ni][0] = *(const unsigned*)&Bh[bbase];
                bh[ni][1] = *(const unsigned*)&Bh[bbase + 8];
                bl[ni][0] = *(const unsigned*)&Bl[bbase];
                bl[ni][1] = *(const unsigned*)&Bl[bbase + 8];
            }
            #pragma unroll
            for (int mi = 0; mi < 2; mi++) {
                int row0 = (warp_m * 32 + mi * 16 + g) * ASTRIDE + kh + 2 * tg;
                int row1 = row0 + 8 * ASTRIDE;
                float2 v00 = *(const float2*)&Af[row0];
                float2 v10 = *(const float2*)&Af[row1];
                float2 v01 = *(const float2*)&Af[row0 + 8];
                float2 v11 = *(const float2*)&Af[row1 + 8];
                unsigned ah[4], al[4];
                split2(v00, ah[0], al[0]);
                split2(v10, ah[1], al[1]);
                split2(v01, ah[2], al[2]);
                split2(v11, ah[3], al[3]);
                #pragma unroll
                for (int ni = 0; ni < 4; ni++) {
                    mma16816(c[mi][ni], ah, bh[ni]);
                    mma16816(c[mi][ni], al, bh[ni]);
                    mma16816(c[mi][ni], ah, bl[ni]);
                }
            }
        }
        __syncthreads();
        if (kt < 2) {
            load_A(kt + 2, kt & 1);
            asm volatile("cp.async.commit_group;" ::: "memory");
            asm volatile("cp.async.wait_group 1;" ::: "memory");
            __syncthreads();
        } else if (kt == 2) {
            asm volatile("cp.async.wait_group 0;" ::: "memory");
            __syncthreads();
        }
    }

    // epilogue: xs -> fp16 ; xf = y[:, 64:] + bf1 (fp32)
    float* xff = (float*)g_xf;
    #pragma unroll
    for (int mi = 0; mi < 2; mi++) {
        int rA = bm + warp_m * 32 + mi * 16 + g;
        int rB = rA + 8;
        #pragma unroll
        for (int ni = 0; ni < 4; ni++) {
            int col = warp_n * 32 + ni * 8 + 2 * tg;
            if (warp_n < 2) {
                if (rA < N)
                    *(__half2*)&g_xsh[(long long)rA * 64 + col] =
                        __floats2half2_rn(c[mi][ni][0], c[mi][ni][1]);
                if (rB < N)
                    *(__half2*)&g_xsh[(long long)rB * 64 + col] =
                        __floats2half2_rn(c[mi][ni][2], c[mi][ni][3]);
            } else {
                int cf = col - 64;
                float b0 = bf1[cf], b1v = bf1[cf + 1];
                if (rA < N)
                    *(float2*)&xff[(long long)rA * 64 + cf] =
                        make_float2(c[mi][ni][0] + b0, c[mi][ni][1] + b1v);
                if (rB < N)
                    *(float2*)&xff[(long long)rB * 64 + cf] =
                        make_float2(c[mi][ni][2] + b0, c[mi][ni][3] + b1v);
            }
        }
    }
}

// ---------------- fused gather-aggregate + relu + layer-2 dots ----------------
__global__ __launch_bounds__(256) void aggfin_kernel(
    const float* __restrict__ b1,
    const float* __restrict__ W2,  const float* __restrict__ b2,
    const float* __restrict__ Wf2, const float* __restrict__ bf2,
    float* __restrict__ out, int N)
{
    int gwarp = (blockIdx.x * 256 + threadIdx.x) >> 5;
    int lane  = threadIdx.x & 31;
    if (gwarp >= N) return;
    const int half = lane >> 4;
    const int lq   = lane & 15;

    const uint2* __restrict__ xsv = (const uint2*)g_xsh;
    const float4* __restrict__ xf4 = g_xf;
    const float* __restrict__ dptr = g_dinv;
    const int*  __restrict__ srcp = g_src;

    float4 accA = make_float4(0.f, 0.f, 0.f, 0.f);
    float4 accB = make_float4(0.f, 0.f, 0.f, 0.f);

    const int rs  = g_rowstart[gwarp];
    const int deg = g_deg[gwarp];

    int k = half;
    for (; k + 6 < deg; k += 8) {
        int s0 = __ldg(srcp + rs + k);
        int s1 = __ldg(srcp + rs + k + 2);
        int s2 = __ldg(srcp + rs + k + 4);
        int s3 = __ldg(srcp + rs + k + 6);
        float w0 = __ldg(dptr + s0);
        float w1 = __ldg(dptr + s1);
        float w2 = __ldg(dptr + s2);
        float w3 = __ldg(dptr + s3);
        uint2 u0 = __ldg(xsv + s0 * 16 + lq);
        uint2 u1 = __ldg(xsv + s1 * 16 + lq);
        uint2 u2 = __ldg(xsv + s2 * 16 + lq);
        uint2 u3 = __ldg(xsv + s3 * 16 + lq);
        float2 p0 = __half22float2(*(__half2*)&u0.x), q0 = __half22float2(*(__half2*)&u0.y);
        float2 p1 = __half22float2(*(__half2*)&u1.x), q1 = __half22float2(*(__half2*)&u1.y);
        float2 p2 = __half22float2(*(__half2*)&u2.x), q2 = __half22float2(*(__half2*)&u2.y);
        float2 p3 = __half22float2(*(__half2*)&u3.x), q3 = __half22float2(*(__half2*)&u3.y);
        accA.x = fmaf(w0, p0.x, accA.x); accA.y = fmaf(w0, p0.y, accA.y);
        accA.z = fmaf(w0, q0.x, accA.z); accA.w = fmaf(w0, q0.y, accA.w);
        accB.x = fmaf(w1, p1.x, accB.x); accB.y = fmaf(w1, p1.y, accB.y);
        accB.z = fmaf(w1, q1.x, accB.z); accB.w = fmaf(w1, q1.y, accB.w);
        accA.x = fmaf(w2, p2.x, accA.x); accA.y = fmaf(w2, p2.y, accA.y);
        accA.z = fmaf(w2, q2.x, accA.z); accA.w = fmaf(w2, q2.y, accA.w);
        accB.x = fmaf(w3, p3.x, accB.x); accB.y = fmaf(w3, p3.y, accB.y);
        accB.z = fmaf(w3, q3.x, accB.z); accB.w = fmaf(w3, q3.y, accB.w);
    }
    for (; k < deg; k += 2) {
        int s0 = __ldg(srcp + rs + k);
        float w = __ldg(dptr + s0);
        uint2 u0 = __ldg(xsv + s0 * 16 + lq);
        float2 p0 = __half22float2(*(__half2*)&u0.x), q0 = __half22float2(*(__half2*)&u0.y);
        accA.x = fmaf(w, p0.x, accA.x); accA.y = fmaf(w, p0.y, accA.y);
        accA.z = fmaf(w, q0.x, accA.z); accA.w = fmaf(w, q0.y, accA.w);
    }
    accA.x += accB.x; accA.y += accB.y; accA.z += accB.z; accA.w += accB.w;
    accA.x += __shfl_xor_sync(0xFFFFFFFFu, accA.x, 16);
    accA.y += __shfl_xor_sync(0xFFFFFFFFu, accA.y, 16);
    accA.z += __shfl_xor_sync(0xFFFFFFFFu, accA.z, 16);
    accA.w += __shfl_xor_sync(0xFFFFFFFFu, accA.w, 16);

    float dv = dptr[gwarp];
    {   // self term
        uint2 u0 = __ldg(xsv + gwarp * 16 + lq);
        float2 p0 = __half22float2(*(__half2*)&u0.x), q0 = __half22float2(*(__half2*)&u0.y);
        accA.x = fmaf(dv, p0.x, accA.x); accA.y = fmaf(dv, p0.y, accA.y);
        accA.z = fmaf(dv, q0.x, accA.z); accA.w = fmaf(dv, q0.y, accA.w);
    }

    int c0 = lq * 4;
    float s, tt;
    if (half == 0) {
        float a0 = fmaxf(dv * accA.x + b1[c0],     0.f);
        float a1 = fmaxf(dv * accA.y + b1[c0 + 1], 0.f);
        float a2 = fmaxf(dv * accA.z + b1[c0 + 2], 0.f);
        float a3 = fmaxf(dv * accA.w + b1[c0 + 3], 0.f);
        s  = a0 * W2[c0]  + a1 * W2[c0 + 1]  + a2 * W2[c0 + 2]  + a3 * W2[c0 + 3];
        tt = a0 * Wf2[c0] + a1 * Wf2[c0 + 1] + a2 * Wf2[c0 + 2] + a3 * Wf2[c0 + 3];
    } else {
        float4 fv = __ldg(&xf4[(long long)gwarp * 16 + lq]);
        float f0 = fmaxf(fv.x, 0.f);
        float f1 = fmaxf(fv.y, 0.f);
        float f2 = fmaxf(fv.z, 0.f);
        float f3 = fmaxf(fv.w, 0.f);
        s  = f0 * W2[64 + c0]  + f1 * W2[65 + c0]  + f2 * W2[66 + c0]  + f3 * W2[67 + c0];
        tt = f0 * Wf2[64 + c0] + f1 * Wf2[65 + c0] + f2 * Wf2[66 + c0] + f3 * Wf2[67 + c0];
    }
    #pragma unroll
    for (int o = 16; o > 0; o >>= 1) {
        s  += __shfl_xor_sync(0xFFFFFFFFu, s, o);
        tt += __shfl_xor_sync(0xFFFFFFFFu, tt, o);
    }
    if (lane == 0) {
        float u = dv * s;
        g_u[gwarp] = u;
        out[gwarp] = b2[0] + bf2[0] + tt + dv * u;
    }
}

// ---------------- layer-2 gather ----------------
__global__ __launch_bounds__(256) void fin2_kernel(float* __restrict__ out, int N) {
    int gwarp = (blockIdx.x * 256 + threadIdx.x) >> 5;
    int lane  = threadIdx.x & 31;
    if (gwarp >= N) return;
    int rs  = g_rowstart[gwarp];
    int deg = g_deg[gwarp];
    float acc = 0.f;
    for (int i = lane; i < deg; i += 32)
        acc += __ldg(&g_u[g_src[rs + i]]);
    #pragma unroll
    for (int o = 16; o > 0; o >>= 1)
        acc += __shfl_xor_sync(0xFFFFFFFFu, acc, o);
    if (lane == 0)
        out[gwarp] += g_dinv[gwarp] * acc;
}

// ---------------- launch: prepA[0] count[1] wprep[2] gemm[3] scan[4] scatter[5]
extern "C" void kernel_launch(void* const* d_in, const int* in_sizes, int n_in,
                              void* d_out, int out_size) {
    const float* x   = (const float*)d_in[0];
    const void*  ei  = d_in[1];
    const float* W1  = (const float*)d_in[2];
    const float* b1  = (const float*)d_in[3];
    const float* Wf1 = (const float*)d_in[4];
    const float* bf1 = (const float*)d_in[5];
    const float* W2  = (const float*)d_in[6];
    const float* b2  = (const float*)d_in[7];
    const float* Wf2 = (const float*)d_in[8];
    const float* bf2 = (const float*)d_in[9];
    float* out = (float*)d_out;

    int N = in_sizes[0] / FIN;
    long long E = (long long)in_sizes[1] / 2;
    int nb = (N + 255) / 256;
    int eb4 = (int)((E + 1023) / 1024);

    static cudaStream_t s1 = nullptr;
    static cudaEvent_t ev0 = nullptr, evB = nullptr;
    if (!s1) {
        cudaStreamCreateWithFlags(&s1, cudaStreamNonBlocking);
        cudaEventCreateWithFlags(&ev0, cudaEventDisableTiming);
        cudaEventCreateWithFlags(&evB, cudaEventDisableTiming);
        cudaFuncSetAttribute(gemm_kernel, cudaFuncAttributeMaxDynamicSharedMemorySize,
                             DSMEM_BYTES);
    }
    cudaStream_t s0 = 0;

    int nwords = (E < 2048) ? (int)E : 2048;
    // [0] prepA (detect + zero + part init)
    prepA_kernel<<<1 + nb, 256, 0, s0>>>((const unsigned long long*)ei, nwords, N);
    cudaEventRecord(ev0, s0);

    // [1] count on s1
    cudaStreamWaitEvent(s1, ev0, 0);
    count_kernel<<<eb4, 256, 0, s1>>>(ei, E);

    // [2] wprep, [3] gemm on s0 (gemm = profiled slot)
    wprep_kernel<<<64, 256, 0, s0>>>(W1, Wf1);
    gemm_kernel<<<(N + 63) / 64, 256, DSMEM_BYTES, s0>>>(x, bf1, N);

    // [4] scan, [5] scatter on s1 (co-runs with gemm now that regs/threads are free)
    scan_kernel<<<nb, 256, 0, s1>>>(N);
    scatter_kernel<<<eb4, 256, 0, s1>>>(ei, E);
    cudaEventRecord(evB, s1);

    // [6] aggfin, [7] fin2
    cudaStreamWaitEvent(s0, evB, 0);
    int wb = (int)(((long long)N * 32 + 255) / 256);
    aggfin_kernel<<<wb, 256, 0, s0>>>(b1, W2, b2, Wf2, bf2, out, N);
    fin2_kernel<<<wb, 256, 0, s0>>>(out, N);
}